// round 1
// baseline (speedup 1.0000x reference)
#include <cuda_runtime.h>
#include <math.h>
#include <stdint.h>

// ---------------- problem constants ----------------
#define kNQ 10000
#define kNS 500
#define kQN 4
#define kSN 10
#define kB  32
#define kS  200
#define kD  128
#define kT  199   // S-1

// ---------------- scratch layout (floats) ----------------
__host__ __device__ constexpr size_t O_TA0 = 0;
__host__ __device__ constexpr size_t O_TA1 = O_TA0 + (size_t)kNQ*kD;
__host__ __device__ constexpr size_t O_TA2 = O_TA1 + (size_t)kNS*kD;
__host__ __device__ constexpr size_t O_TB0 = O_TA2 + (size_t)kNQ*kD;
__host__ __device__ constexpr size_t O_TB1 = O_TB0 + (size_t)kNQ*kD;
__host__ __device__ constexpr size_t O_TC0 = O_TB1 + (size_t)kNS*kD;
__host__ __device__ constexpr size_t O_A   = O_TC0 + (size_t)kNQ*kD;
__host__ __device__ constexpr size_t O_QT  = O_A   + (size_t)kNQ*kD;
__host__ __device__ constexpr size_t O_G   = O_QT  + (size_t)kB*kS*kD;
__host__ __device__ constexpr size_t O_H   = O_G   + (size_t)kB*kS*3*kD;
__host__ __device__ constexpr size_t O_AS  = O_H   + (size_t)kB*kS*kD;
__host__ __device__ constexpr size_t O_PM  = O_AS  + (size_t)kB*kT;
__host__ __device__ constexpr size_t O_V   = O_PM  + (size_t)kB*kT;   // qv[128], kv[128], c_q, c_k
__host__ __device__ constexpr size_t O_RG  = O_V   + 258;             // r_gates 2x512
__host__ __device__ constexpr size_t G_TOTAL = O_RG + 1024;

__device__ float g_buf[G_TOTAL];

// ---------------- prep: rank-1 attention vectors + response gate table ----------------
__global__ void prep_kernel(const float* __restrict__ qW, const float* __restrict__ qb,
                            const float* __restrict__ kW, const float* __restrict__ kb,
                            const float* __restrict__ wW,
                            const float* __restrict__ embr, const float* __restrict__ Wih,
                            const float* __restrict__ bih, const float* __restrict__ bhh)
{
    float* vec = g_buf + O_V;
    float* rg  = g_buf + O_RG;
    int t = threadIdx.x;                 // 512 threads
    if (t < kD) {
        float sq = 0.f, sk = 0.f;
        #pragma unroll 4
        for (int j = 0; j < kD; j++) {
            sq += qW[t*kD + j] * wW[j];
            sk += kW[t*kD + j] * wW[kD + j];
        }
        vec[t]      = sq;
        vec[kD + t] = sk;
    }
    if (t == 256) {
        float s = 0.f;
        for (int j = 0; j < kD; j++) s += qb[j] * wW[j];
        vec[256] = s;
    }
    if (t == 257) {
        float s = 0.f;
        for (int j = 0; j < kD; j++) s += kb[j] * wW[kD + j];
        vec[257] = s;
    }
    // r_gates[r][c] = emb_r[r] @ W_ih[128:,:][:,c] + b_ih[c] + b_hh[c]
    for (int r = 0; r < 2; r++) {
        float s = bih[t] + bhh[t];
        #pragma unroll 4
        for (int k = 0; k < kD; k++)
            s += embr[r*kD + k] * Wih[(size_t)(kD + k)*512 + t];
        rg[r*512 + t] = s;
    }
}

// ---------------- fused gather-mean + 128xN GEMM + activation ----------------
// row_vec[r] = base[rowmap?rowmap[r]:r] + invk * sum_j tbl[nbrs[r][j]]
// out[r, 0:128] = act( row_vec @ W(128 x 128 slice, row stride ldw) [+ bias] [+ addtbl[addidx[r]]] )
// act: 0 = tanh, 1 = relu, 2 = none
__global__ void hop_kernel(const float* __restrict__ base,
                           const int*   __restrict__ rowmap,
                           const int*   __restrict__ nbrs, int knbr, float invk,
                           const float* __restrict__ tbl,
                           const float* __restrict__ W, int ldw,
                           const float* __restrict__ bias,
                           const float* __restrict__ addtbl, const int* __restrict__ addidx,
                           float* __restrict__ out, int ldo,
                           int R, int act)
{
    extern __shared__ float sm[];
    float* sW  = sm;                // 128*128
    float* sIn = sm + kD*kD;        // 64*132 (padded)
    const int tid = threadIdx.x;    // 256

    // load W tile (128x128) into smem
    for (int i = tid; i < kD*32; i += 256) {
        int k = i >> 5, c4 = i & 31;
        ((float4*)(sW + k*kD))[c4] = ((const float4*)(W + (size_t)k*ldw))[c4];
    }

    // build 64 input rows (4 threads per row, 32 dims each)
    const int row0 = blockIdx.x * 64;
    {
        int lr = tid >> 2, part = tid & 3;
        int gr = row0 + lr;
        int d0 = part * 32;
        float v[32];
        if (gr < R) {
            int br = rowmap ? rowmap[gr] : gr;
            const float* bp = base + (size_t)br*kD + d0;
            #pragma unroll
            for (int d = 0; d < 32; d++) v[d] = bp[d];
            if (knbr > 0) {
                float s[32];
                #pragma unroll
                for (int d = 0; d < 32; d++) s[d] = 0.f;
                for (int j = 0; j < knbr; j++) {
                    int nb = nbrs[(size_t)gr*knbr + j];
                    const float* tp = tbl + (size_t)nb*kD + d0;
                    #pragma unroll
                    for (int d = 0; d < 32; d++) s[d] += tp[d];
                }
                #pragma unroll
                for (int d = 0; d < 32; d++) v[d] += s[d] * invk;
            }
        } else {
            #pragma unroll
            for (int d = 0; d < 32; d++) v[d] = 0.f;
        }
        #pragma unroll
        for (int d = 0; d < 32; d++) sIn[lr*132 + d0 + d] = v[d];
    }
    __syncthreads();

    // 64x128 GEMM: each thread computes 4 rows x 8 cols
    const int r0 = (tid >> 4) * 4;   // 0..60
    const int c0 = (tid & 15) * 8;   // 0..120
    float acc[4][8];
    #pragma unroll
    for (int i = 0; i < 4; i++)
        #pragma unroll
        for (int j = 0; j < 8; j++) acc[i][j] = 0.f;

    #pragma unroll 4
    for (int k = 0; k < kD; k++) {
        float a0 = sIn[(r0+0)*132 + k];
        float a1 = sIn[(r0+1)*132 + k];
        float a2 = sIn[(r0+2)*132 + k];
        float a3 = sIn[(r0+3)*132 + k];
        float4 b0 = *(const float4*)(sW + k*kD + c0);
        float4 b1 = *(const float4*)(sW + k*kD + c0 + 4);
        float bb[8] = {b0.x,b0.y,b0.z,b0.w,b1.x,b1.y,b1.z,b1.w};
        #pragma unroll
        for (int j = 0; j < 8; j++) {
            acc[0][j] += a0*bb[j];
            acc[1][j] += a1*bb[j];
            acc[2][j] += a2*bb[j];
            acc[3][j] += a3*bb[j];
        }
    }

    #pragma unroll
    for (int i = 0; i < 4; i++) {
        int gr = row0 + r0 + i;
        if (gr >= R) continue;
        int aidx = addidx ? addidx[gr] : 0;
        #pragma unroll
        for (int j = 0; j < 8; j++) {
            int c = c0 + j;
            float vv = acc[i][j];
            if (bias)   vv += bias[c];
            if (addtbl) vv += addtbl[(size_t)aidx*512 + c];
            if (act == 0)      vv = tanhf(vv);
            else if (act == 1) vv = fmaxf(vv, 0.f);
            out[(size_t)gr*ldo + c] = vv;
        }
    }
}

// ---------------- pointwise "LSTM" (no recurrence; f gate dead) ----------------
__global__ void h_kernel()
{
    const float* gates = g_buf + O_G;
    float* h = g_buf + O_H;
    int idx = blockIdx.x * blockDim.x + threadIdx.x;
    if (idx >= kB*kS*kD) return;
    int r = idx / kD, d = idx % kD;
    float gi = gates[(size_t)r*384 + d];
    float gg = gates[(size_t)r*384 + 128 + d];
    float go = gates[(size_t)r*384 + 256 + d];
    float c  = (1.f/(1.f + expf(-gi))) * tanhf(gg);
    h[idx]   = (1.f/(1.f + expf(-go))) * tanhf(c);
}

// ---------------- a_state = h . qv + c_q (one warp per row) ----------------
__global__ void astate_kernel()
{
    const float* h   = g_buf + O_H;
    const float* vec = g_buf + O_V;
    float* as        = g_buf + O_AS;
    int row = blockIdx.x * 8 + (threadIdx.x >> 5);
    if (row >= kB*kT) return;
    int b = row / kT, n = row % kT;
    int lane = threadIdx.x & 31;
    const float* hr = h + ((size_t)b*kS + n)*kD;
    float s = 0.f;
    #pragma unroll
    for (int d = lane; d < kD; d += 32) s += hr[d] * vec[d];
    #pragma unroll
    for (int o = 16; o; o >>= 1) s += __shfl_down_sync(0xffffffffu, s, o);
    if (lane == 0) as[row] = s + vec[256];
}

// ---------------- prefix max of a_state per batch ----------------
__global__ void pmax_kernel()
{
    const float* as = g_buf + O_AS;
    float* pm       = g_buf + O_PM;
    int b = threadIdx.x;
    if (b >= kB) return;
    float m = -INFINITY;
    for (int n = 0; n < kT; n++) {
        m = fmaxf(m, as[b*kT + n]);
        pm[b*kT + n] = m;
    }
}

// ---------------- fused attention + prediction ----------------
// alpha[n,m] factorizes: softmax_n(a_state | n<=t) (x) softmax_m(a_qs[t,:]); w_b cancels.
__global__ void pred_kernel(const int* __restrict__ question,
                            const int* __restrict__ qs_skills,
                            const float* __restrict__ emb_q,
                            const float* __restrict__ emb_s,
                            float* __restrict__ out)
{
    const float* h   = g_buf + O_H;
    const float* as  = g_buf + O_AS;
    const float* pm  = g_buf + O_PM;
    const float* vec = g_buf + O_V;

    __shared__ float sqs[5][kD];
    __shared__ float sred[4];
    __shared__ float sr[5];
    __shared__ float sM1;
    __shared__ float sv[4], se2[4];

    int t = blockIdx.x, b = blockIdx.y;
    int tid = threadIdx.x;              // 128
    int q = question[b*kS + t + 1];

    sqs[0][tid] = emb_q[(size_t)q*kD + tid];
    #pragma unroll
    for (int m = 1; m < 5; m++) {
        int si = qs_skills[q*4 + m - 1];
        sqs[m][tid] = emb_s[(size_t)si*kD + tid];
    }
    float kvd = vec[kD + tid];
    __syncthreads();

    // a_qs[m] via block reduction
    #pragma unroll
    for (int m = 0; m < 5; m++) {
        float p = sqs[m][tid] * kvd;
        #pragma unroll
        for (int o = 16; o; o >>= 1) p += __shfl_down_sync(0xffffffffu, p, o);
        if ((tid & 31) == 0) sred[tid >> 5] = p;
        __syncthreads();
        if (tid == 0) sr[m] = sred[0] + sred[1] + sred[2] + sred[3];
        __syncthreads();
    }
    if (tid == 0) {
        float ck = vec[257];
        float a[5], mx = -INFINITY;
        #pragma unroll
        for (int m = 0; m < 5; m++) { a[m] = sr[m] + ck; mx = fmaxf(mx, a[m]); }
        float se = 0.f;
        #pragma unroll
        for (int m = 0; m < 5; m++) { a[m] = expf(a[m] - mx); se += a[m]; }
        #pragma unroll
        for (int m = 0; m < 5; m++) sr[m] = a[m] / se;
        sM1 = pm[b*kT + t];
    }
    __syncthreads();

    float r0 = sr[0], r1 = sr[1], r2 = sr[2], r3 = sr[3], r4 = sr[4];
    float M1 = sM1;
    float sum_v = 0.f, sum_e = 0.f;

    for (int n = tid; n <= t; n += 128) {
        float e = expf(as[b*kT + n] - M1);
        const float4* hr = (const float4*)(h + ((size_t)b*kS + n)*kD);
        float in0 = 0.f, in1 = 0.f, in2 = 0.f, in3 = 0.f, in4 = 0.f;
        #pragma unroll 8
        for (int d4 = 0; d4 < 32; d4++) {
            float4 hv = hr[d4];
            int dd = d4 * 4;
            in0 += hv.x*sqs[0][dd] + hv.y*sqs[0][dd+1] + hv.z*sqs[0][dd+2] + hv.w*sqs[0][dd+3];
            in1 += hv.x*sqs[1][dd] + hv.y*sqs[1][dd+1] + hv.z*sqs[1][dd+2] + hv.w*sqs[1][dd+3];
            in2 += hv.x*sqs[2][dd] + hv.y*sqs[2][dd+1] + hv.z*sqs[2][dd+2] + hv.w*sqs[2][dd+3];
            in3 += hv.x*sqs[3][dd] + hv.y*sqs[3][dd+1] + hv.z*sqs[3][dd+2] + hv.w*sqs[3][dd+3];
            in4 += hv.x*sqs[4][dd] + hv.y*sqs[4][dd+1] + hv.z*sqs[4][dd+2] + hv.w*sqs[4][dd+3];
        }
        float s0 = 1.f/(1.f + expf(-in0));
        float s1 = 1.f/(1.f + expf(-in1));
        float s2 = 1.f/(1.f + expf(-in2));
        float s3 = 1.f/(1.f + expf(-in3));
        float s4 = 1.f/(1.f + expf(-in4));
        sum_v += e * (r0*s0 + r1*s1 + r2*s2 + r3*s3 + r4*s4);
        sum_e += e;
    }
    #pragma unroll
    for (int o = 16; o; o >>= 1) {
        sum_v += __shfl_down_sync(0xffffffffu, sum_v, o);
        sum_e += __shfl_down_sync(0xffffffffu, sum_e, o);
    }
    if ((tid & 31) == 0) { sv[tid >> 5] = sum_v; se2[tid >> 5] = sum_e; }
    __syncthreads();
    if (tid == 0) {
        float V = sv[0] + sv[1] + sv[2] + sv[3];
        float E = se2[0] + se2[1] + se2[2] + se2[3];
        out[b*kS + t + 1] = V / E;
        if (t == 0) out[b*kS] = 0.f;
    }
}

// ---------------- launch ----------------
extern "C" void kernel_launch(void* const* d_in, const int* in_sizes, int n_in,
                              void* d_out, int out_size)
{
    const int*   question = (const int*)  d_in[0];
    const int*   response = (const int*)  d_in[1];
    // d_in[2] = mask (unused by reference)
    const int*   q_nbr    = (const int*)  d_in[3];
    const int*   s_nbr    = (const int*)  d_in[4];
    const int*   qs_sk    = (const int*)  d_in[5];
    const float* emb_q    = (const float*)d_in[6];
    const float* emb_s    = (const float*)d_in[7];
    const float* emb_r    = (const float*)d_in[8];
    const float* W_ih     = (const float*)d_in[9];
    const float* b_ih     = (const float*)d_in[10];
    const float* b_hh     = (const float*)d_in[11];
    const float* ft_W     = (const float*)d_in[12];
    const float* ft_b     = (const float*)d_in[13];
    const float* agg_W    = (const float*)d_in[14];
    const float* agg_b    = (const float*)d_in[15];
    const float* last_W   = (const float*)d_in[16];
    const float* last_b   = (const float*)d_in[17];
    const float* q_W      = (const float*)d_in[18];
    const float* q_b      = (const float*)d_in[19];
    const float* k_W      = (const float*)d_in[20];
    const float* k_b      = (const float*)d_in[21];
    const float* w_W      = (const float*)d_in[22];
    // d_in[23] = w_b: cancels inside the softmax, unused
    float* out = (float*)d_out;

    float* buf = nullptr;
    cudaGetSymbolAddress((void**)&buf, g_buf);
    float* TA0 = buf + O_TA0;
    float* TA1 = buf + O_TA1;
    float* TA2 = buf + O_TA2;
    float* TB0 = buf + O_TB0;
    float* TB1 = buf + O_TB1;
    float* TC0 = buf + O_TC0;
    float* A   = buf + O_A;
    float* QT  = buf + O_QT;
    float* G   = buf + O_G;
    float* RG  = buf + O_RG;

    const int HOP_SMEM = (128*128 + 64*132) * (int)sizeof(float);
    cudaFuncSetAttribute(hop_kernel, cudaFuncAttributeMaxDynamicSharedMemorySize, HOP_SMEM);

    prep_kernel<<<1, 512>>>(q_W, q_b, k_W, k_b, w_W, emb_r, W_ih, b_ih, b_hh);

    const int gq = (kNQ + 63) / 64;        // 157
    const int gs = (kNS + 63) / 64;        // 8
    const int gr = (kB*kS + 63) / 64;      // 100

    // hop i=0 (tables over index spaces)
    hop_kernel<<<gq, 256, HOP_SMEM>>>(emb_q, nullptr, q_nbr, kQN, 1.f/kQN, emb_s,
                                      agg_W,            128, agg_b,       nullptr, nullptr,
                                      TA0, 128, kNQ, 0);
    hop_kernel<<<gq, 256, HOP_SMEM>>>(emb_q, nullptr, q_nbr, kQN, 1.f/kQN, emb_s,
                                      agg_W + 2*16384,  128, agg_b + 256, nullptr, nullptr,
                                      TA2, 128, kNQ, 0);
    hop_kernel<<<gs, 256, HOP_SMEM>>>(emb_s, nullptr, s_nbr, kSN, 1.f/kSN, emb_q,
                                      agg_W + 16384,    128, agg_b + 128, nullptr, nullptr,
                                      TA1, 128, kNS, 0);
    // hop i=1
    hop_kernel<<<gq, 256, HOP_SMEM>>>(TA0, nullptr, q_nbr, kQN, 1.f/kQN, TA1,
                                      agg_W,            128, agg_b,       nullptr, nullptr,
                                      TB0, 128, kNQ, 0);
    hop_kernel<<<gs, 256, HOP_SMEM>>>(TA1, nullptr, s_nbr, kSN, 1.f/kSN, TA2,
                                      agg_W + 16384,    128, agg_b + 128, nullptr, nullptr,
                                      TB1, 128, kNS, 0);
    // hop i=2
    hop_kernel<<<gq, 256, HOP_SMEM>>>(TB0, nullptr, q_nbr, kQN, 1.f/kQN, TB1,
                                      agg_W,            128, agg_b,       nullptr, nullptr,
                                      TC0, 128, kNQ, 0);
    // last projection
    hop_kernel<<<gq, 256, HOP_SMEM>>>(TC0, nullptr, nullptr, 0, 0.f, nullptr,
                                      last_W,           128, last_b,      nullptr, nullptr,
                                      A, 128, kNQ, 0);
    // q_trans = relu(A[question] @ ft_W + ft_b)
    hop_kernel<<<gr, 256, HOP_SMEM>>>(A, question, nullptr, 0, 0.f, nullptr,
                                      ft_W,             128, ft_b,        nullptr, nullptr,
                                      QT, 128, kB*kS, 1);
    // gates (only i,g,o columns of W_ih; bias + response part folded into RG)
    const int coloff[3] = {0, 256, 384};
    for (int grp = 0; grp < 3; grp++) {
        hop_kernel<<<gr, 256, HOP_SMEM>>>(QT, nullptr, nullptr, 0, 0.f, nullptr,
                                          W_ih + coloff[grp], 512, nullptr,
                                          RG + coloff[grp], response,
                                          G + grp*128, 384, kB*kS, 2);
    }

    h_kernel<<<(kB*kS*kD + 255)/256, 256>>>();
    astate_kernel<<<(kB*kT + 7)/8, 256>>>();
    pmax_kernel<<<1, 32>>>();

    dim3 pg(kT, kB);
    pred_kernel<<<pg, 128>>>(question, qs_sk, emb_q, emb_s, out);
}

// round 2
// speedup vs baseline: 1.6745x; 1.6745x over previous
#include <cuda_runtime.h>
#include <math.h>
#include <stdint.h>

// ---------------- problem constants ----------------
#define kNQ 10000
#define kNS 500
#define kQN 4
#define kSN 10
#define kB  32
#define kS  200
#define kD  128
#define kT  199   // S-1

// ---------------- scratch layout (floats) ----------------
__host__ __device__ constexpr size_t O_TA0 = 0;
__host__ __device__ constexpr size_t O_TA1 = O_TA0 + (size_t)kNQ*kD;
__host__ __device__ constexpr size_t O_TA2 = O_TA1 + (size_t)kNS*kD;
__host__ __device__ constexpr size_t O_TB0 = O_TA2 + (size_t)kNQ*kD;
__host__ __device__ constexpr size_t O_TB1 = O_TB0 + (size_t)kNQ*kD;
__host__ __device__ constexpr size_t O_TC0 = O_TB1 + (size_t)kNS*kD;
__host__ __device__ constexpr size_t O_A   = O_TC0 + (size_t)kNQ*kD;
__host__ __device__ constexpr size_t O_H   = O_A   + (size_t)kNQ*kD;
__host__ __device__ constexpr size_t O_AS  = O_H   + (size_t)kB*kS*kD;
__host__ __device__ constexpr size_t O_V   = O_AS  + (size_t)kB*kT;   // qv[128], kv[128], c_q, c_k
__host__ __device__ constexpr size_t O_RG  = O_V   + 258;             // r_gates 2x512
__host__ __device__ constexpr size_t G_TOTAL = O_RG + 1024;

__device__ float g_buf[G_TOTAL];

// ---------------- fast math ----------------
__device__ __forceinline__ float fast_tanh(float x) {
    float y;
    asm("tanh.approx.f32 %0, %1;" : "=f"(y) : "f"(x));
    return y;
}
__device__ __forceinline__ float fast_sigmoid(float x) {
    return 0.5f * fast_tanh(0.5f * x) + 0.5f;
}

// ---------------- prep: rank-1 attention vectors + response gate table ----------------
__global__ void prep_kernel(const float* __restrict__ qW, const float* __restrict__ qb,
                            const float* __restrict__ kW, const float* __restrict__ kb,
                            const float* __restrict__ wW,
                            const float* __restrict__ embr, const float* __restrict__ Wih,
                            const float* __restrict__ bih, const float* __restrict__ bhh)
{
    float* vec = g_buf + O_V;
    float* rg  = g_buf + O_RG;
    int t = threadIdx.x;                 // 512 threads
    if (t < kD) {
        float sq = 0.f, sk = 0.f;
        #pragma unroll 4
        for (int j = 0; j < kD; j++) {
            sq += qW[t*kD + j] * wW[j];
            sk += kW[t*kD + j] * wW[kD + j];
        }
        vec[t]      = sq;
        vec[kD + t] = sk;
    }
    if (t == 256) {
        float s = 0.f;
        for (int j = 0; j < kD; j++) s += qb[j] * wW[j];
        vec[256] = s;
    }
    if (t == 257) {
        float s = 0.f;
        for (int j = 0; j < kD; j++) s += kb[j] * wW[kD + j];
        vec[257] = s;
    }
    for (int r = 0; r < 2; r++) {
        float s = bih[t] + bhh[t];
        #pragma unroll 4
        for (int k = 0; k < kD; k++)
            s += embr[r*kD + k] * Wih[(size_t)(kD + k)*512 + t];
        rg[r*512 + t] = s;
    }
}

// ---------------- fused multi-task hop kernel ----------------
// per task: out[r] = tanh( (base[r] + invk * sum_j tbl[nbrs[r][j]]) @ W + bias )
struct HopTask {
    const float* base;
    const int*   nbrs;
    const float* tbl;
    const float* W;
    const float* bias;
    float*       out;
    int knbr; float invk;
    int R; int blk0;
};
struct HopParams { HopTask t[3]; int nt; };

__global__ __launch_bounds__(256, 2) void hop_kernel(const HopParams p)
{
    extern __shared__ float sm[];
    float* sW  = sm;                 // 128x128
    float* sIn = sm + kD*kD;         // 64x132
    const int tid = threadIdx.x;

    // find my task
    int ti = 0;
    #pragma unroll
    for (int i = 1; i < 3; i++)
        if (i < p.nt && (int)blockIdx.x >= p.t[i].blk0) ti = i;
    const HopTask& T = p.t[ti];
    const int row0 = (blockIdx.x - T.blk0) * 64;

    // load W (128x128) into smem
    for (int i = tid; i < kD*32; i += 256) {
        int k = i >> 5, c4 = i & 31;
        ((float4*)(sW + k*kD))[c4] = __ldg(&((const float4*)(T.W + (size_t)k*kD))[c4]);
    }

    // build 64 input rows (4 threads/row, 32 dims each)
    {
        int lr = tid >> 2, part = tid & 3;
        int gr = row0 + lr;
        int d4base = part * 8;                 // float4 index within row
        float4 v[8];
        if (gr < T.R) {
            const float4* bp = (const float4*)(T.base + (size_t)gr*kD) + d4base;
            #pragma unroll
            for (int d = 0; d < 8; d++) v[d] = __ldg(&bp[d]);
            if (T.knbr > 0) {
                float4 s[8];
                #pragma unroll
                for (int d = 0; d < 8; d++) s[d] = make_float4(0.f,0.f,0.f,0.f);
                for (int j = 0; j < T.knbr; j++) {
                    int nb = __ldg(&T.nbrs[(size_t)gr*T.knbr + j]);
                    const float4* tp = (const float4*)(T.tbl + (size_t)nb*kD) + d4base;
                    #pragma unroll
                    for (int d = 0; d < 8; d++) {
                        float4 x = __ldg(&tp[d]);
                        s[d].x += x.x; s[d].y += x.y; s[d].z += x.z; s[d].w += x.w;
                    }
                }
                #pragma unroll
                for (int d = 0; d < 8; d++) {
                    v[d].x += s[d].x * T.invk; v[d].y += s[d].y * T.invk;
                    v[d].z += s[d].z * T.invk; v[d].w += s[d].w * T.invk;
                }
            }
        } else {
            #pragma unroll
            for (int d = 0; d < 8; d++) v[d] = make_float4(0.f,0.f,0.f,0.f);
        }
        #pragma unroll
        for (int d = 0; d < 8; d++)
            *(float4*)(sIn + lr*132 + (d4base + d)*4) = v[d];
    }
    __syncthreads();

    // 64x128 GEMM: thread tile 4 rows x 8 cols
    const int r0 = (tid >> 4) * 4;
    const int c0 = (tid & 15) * 8;
    float acc[4][8];
    #pragma unroll
    for (int i = 0; i < 4; i++)
        #pragma unroll
        for (int j = 0; j < 8; j++) acc[i][j] = 0.f;

    #pragma unroll 4
    for (int k = 0; k < kD; k++) {
        float a0 = sIn[(r0+0)*132 + k];
        float a1 = sIn[(r0+1)*132 + k];
        float a2 = sIn[(r0+2)*132 + k];
        float a3 = sIn[(r0+3)*132 + k];
        float4 b0 = *(const float4*)(sW + k*kD + c0);
        float4 b1 = *(const float4*)(sW + k*kD + c0 + 4);
        float bb[8] = {b0.x,b0.y,b0.z,b0.w,b1.x,b1.y,b1.z,b1.w};
        #pragma unroll
        for (int j = 0; j < 8; j++) {
            acc[0][j] += a0*bb[j];
            acc[1][j] += a1*bb[j];
            acc[2][j] += a2*bb[j];
            acc[3][j] += a3*bb[j];
        }
    }

    float bsv[8];
    #pragma unroll
    for (int j = 0; j < 8; j++) bsv[j] = __ldg(&T.bias[c0 + j]);

    #pragma unroll
    for (int i = 0; i < 4; i++) {
        int gr = row0 + r0 + i;
        if (gr >= T.R) continue;
        float4 o0, o1;
        o0.x = fast_tanh(acc[i][0] + bsv[0]); o0.y = fast_tanh(acc[i][1] + bsv[1]);
        o0.z = fast_tanh(acc[i][2] + bsv[2]); o0.w = fast_tanh(acc[i][3] + bsv[3]);
        o1.x = fast_tanh(acc[i][4] + bsv[4]); o1.y = fast_tanh(acc[i][5] + bsv[5]);
        o1.z = fast_tanh(acc[i][6] + bsv[6]); o1.w = fast_tanh(acc[i][7] + bsv[7]);
        *(float4*)(T.out + (size_t)gr*kD + c0)     = o0;
        *(float4*)(T.out + (size_t)gr*kD + c0 + 4) = o1;
    }
}

// ---------------- fused row chain: QT -> gates -> h -> a_state ----------------
// 32 rows/block, 256 threads, thread tile 2x8.
__device__ __forceinline__ void gemm32(const float* __restrict__ sIn,
                                       const float* __restrict__ sW,
                                       float acc[2][8], int r0, int c0)
{
    #pragma unroll
    for (int i = 0; i < 2; i++)
        #pragma unroll
        for (int j = 0; j < 8; j++) acc[i][j] = 0.f;
    #pragma unroll 4
    for (int k = 0; k < kD; k++) {
        float a0 = sIn[(r0+0)*132 + k];
        float a1 = sIn[(r0+1)*132 + k];
        float4 b0 = *(const float4*)(sW + k*kD + c0);
        float4 b1 = *(const float4*)(sW + k*kD + c0 + 4);
        float bb[8] = {b0.x,b0.y,b0.z,b0.w,b1.x,b1.y,b1.z,b1.w};
        #pragma unroll
        for (int j = 0; j < 8; j++) {
            acc[0][j] += a0*bb[j];
            acc[1][j] += a1*bb[j];
        }
    }
}

__device__ __forceinline__ void loadW128(float* sW, const float* __restrict__ W,
                                         int ldw, int tid)
{
    for (int i = tid; i < kD*32; i += 256) {
        int k = i >> 5, c4 = i & 31;
        ((float4*)(sW + k*kD))[c4] = __ldg(&((const float4*)(W + (size_t)k*ldw))[c4]);
    }
}

__global__ __launch_bounds__(256, 2) void rowchain_kernel(
    const int* __restrict__ question, const int* __restrict__ response,
    const float* __restrict__ ft_W, const float* __restrict__ ft_b,
    const float* __restrict__ W_ih)
{
    extern __shared__ float sm[];
    float* sW  = sm;               // 128x128 = 64KB
    float* sIn = sm + kD*kD;       // 32x132
    float* sC  = sIn + 32*132;     // 32x132
    float* sqv = sC + 32*132;      // 128

    const float* A   = g_buf + O_A;
    const float* vec = g_buf + O_V;
    const float* RG  = g_buf + O_RG;
    float* H  = g_buf + O_H;
    float* AS = g_buf + O_AS;

    const int tid = threadIdx.x;
    const int row0 = blockIdx.x * 32;
    if (tid < kD) sqv[tid] = vec[tid];

    // gather A[question[row]] into sIn (8 threads/row, 16 dims = 4 float4)
    {
        int lr = tid >> 3, part = tid & 7;
        int grow = row0 + lr;
        int q = __ldg(&question[grow]);
        const float4* ap = (const float4*)(A + (size_t)q*kD) + part*4;
        #pragma unroll
        for (int d = 0; d < 4; d++)
            *(float4*)(sIn + lr*132 + part*16 + d*4) = __ldg(&ap[d]);
    }
    loadW128(sW, ft_W, kD, tid);
    __syncthreads();

    const int r0 = (tid >> 4) * 2;
    const int c0 = (tid & 15) * 8;
    float acc[2][8];

    // stage 1: QT = relu(in @ ft_W + ft_b)
    gemm32(sIn, sW, acc, r0, c0);
    float fb[8];
    #pragma unroll
    for (int j = 0; j < 8; j++) fb[j] = __ldg(&ft_b[c0 + j]);
    __syncthreads();                        // everyone done reading sIn
    #pragma unroll
    for (int i = 0; i < 2; i++)
        #pragma unroll
        for (int j = 0; j < 8; j++)
            sIn[(r0+i)*132 + c0 + j] = fmaxf(acc[i][j] + fb[j], 0.f);
    loadW128(sW, W_ih + 0, 512, tid);       // i-gate cols
    __syncthreads();

    int resp0 = __ldg(&response[row0 + r0]);
    int resp1 = __ldg(&response[row0 + r0 + 1]);

    // stage 2: i gate -> sigmoid -> sC
    gemm32(sIn, sW, acc, r0, c0);
    #pragma unroll
    for (int i = 0; i < 2; i++) {
        int rr = i ? resp1 : resp0;
        #pragma unroll
        for (int j = 0; j < 8; j++)
            sC[(r0+i)*132 + c0 + j] = fast_sigmoid(acc[i][j] + RG[rr*512 + 0 + c0 + j]);
    }
    __syncthreads();
    loadW128(sW, W_ih + 256, 512, tid);     // g-gate cols
    __syncthreads();

    // stage 3: g gate -> c = sig(i)*tanh(g); sC = tanh(c)
    gemm32(sIn, sW, acc, r0, c0);
    #pragma unroll
    for (int i = 0; i < 2; i++) {
        int rr = i ? resp1 : resp0;
        #pragma unroll
        for (int j = 0; j < 8; j++) {
            float gg = acc[i][j] + RG[rr*512 + 256 + c0 + j];
            float cc = sC[(r0+i)*132 + c0 + j] * fast_tanh(gg);
            sC[(r0+i)*132 + c0 + j] = fast_tanh(cc);
        }
    }
    __syncthreads();
    loadW128(sW, W_ih + 384, 512, tid);     // o-gate cols
    __syncthreads();

    // stage 4: o gate -> h = sig(o)*tanh(c)
    gemm32(sIn, sW, acc, r0, c0);
    #pragma unroll
    for (int i = 0; i < 2; i++) {
        int rr = i ? resp1 : resp0;
        int grow = row0 + r0 + i;
        float4 h0, h1;
        float hv[8];
        #pragma unroll
        for (int j = 0; j < 8; j++) {
            float go = acc[i][j] + RG[rr*512 + 384 + c0 + j];
            hv[j] = fast_sigmoid(go) * sC[(r0+i)*132 + c0 + j];
            sC[(r0+i)*132 + c0 + j] = hv[j];
        }
        h0 = make_float4(hv[0],hv[1],hv[2],hv[3]);
        h1 = make_float4(hv[4],hv[5],hv[6],hv[7]);
        *(float4*)(H + (size_t)grow*kD + c0)     = h0;
        *(float4*)(H + (size_t)grow*kD + c0 + 4) = h1;
    }
    __syncthreads();

    // a_state = h . qv + c_q  (8 threads/row)
    {
        int lr = tid >> 3, part = tid & 7;
        int grow = row0 + lr;
        int b = grow / kS, s = grow % kS;
        float p = 0.f;
        #pragma unroll
        for (int d = 0; d < 16; d++)
            p += sC[lr*132 + part*16 + d] * sqv[part*16 + d];
        p += __shfl_down_sync(0xffffffffu, p, 4);
        p += __shfl_down_sync(0xffffffffu, p, 2);
        p += __shfl_down_sync(0xffffffffu, p, 1);
        if (part == 0 && s < kT)
            AS[b*kT + s] = p + vec[256];
    }
}

// ---------------- fused attention + prediction ----------------
__global__ void pred_kernel(const int* __restrict__ question,
                            const int* __restrict__ qs_skills,
                            const float* __restrict__ emb_q,
                            const float* __restrict__ emb_s,
                            float* __restrict__ out)
{
    const float* h   = g_buf + O_H;
    const float* as  = g_buf + O_AS;
    const float* vec = g_buf + O_V;

    __shared__ float sqs[5][kD];
    __shared__ float sred[4];
    __shared__ float sr[5];
    __shared__ float sM1;
    __shared__ float sv[4], se2[4];

    int t = blockIdx.x, b = blockIdx.y;
    int tid = threadIdx.x;              // 128
    int q = __ldg(&question[b*kS + t + 1]);

    sqs[0][tid] = __ldg(&emb_q[(size_t)q*kD + tid]);
    #pragma unroll
    for (int m = 1; m < 5; m++) {
        int si = __ldg(&qs_skills[q*4 + m - 1]);
        sqs[m][tid] = __ldg(&emb_s[(size_t)si*kD + tid]);
    }
    float kvd = vec[kD + tid];
    __syncthreads();

    // a_qs[m] via block reduction
    #pragma unroll
    for (int m = 0; m < 5; m++) {
        float p = sqs[m][tid] * kvd;
        #pragma unroll
        for (int o = 16; o; o >>= 1) p += __shfl_down_sync(0xffffffffu, p, o);
        if ((tid & 31) == 0) sred[tid >> 5] = p;
        __syncthreads();
        if (tid == 0) sr[m] = sred[0] + sred[1] + sred[2] + sred[3];
        __syncthreads();
    }

    // in-block max of a_state over n<=t
    {
        float lm = -INFINITY;
        for (int n = tid; n <= t; n += 128) lm = fmaxf(lm, as[b*kT + n]);
        #pragma unroll
        for (int o = 16; o; o >>= 1) lm = fmaxf(lm, __shfl_down_sync(0xffffffffu, lm, o));
        if ((tid & 31) == 0) sred[tid >> 5] = lm;
        __syncthreads();
        if (tid == 0) {
            sM1 = fmaxf(fmaxf(sred[0], sred[1]), fmaxf(sred[2], sred[3]));
            float ck = vec[257];
            float a[5], mx = -INFINITY;
            #pragma unroll
            for (int m = 0; m < 5; m++) { a[m] = sr[m] + ck; mx = fmaxf(mx, a[m]); }
            float se = 0.f;
            #pragma unroll
            for (int m = 0; m < 5; m++) { a[m] = __expf(a[m] - mx); se += a[m]; }
            float inv = __frcp_rn(se);
            #pragma unroll
            for (int m = 0; m < 5; m++) sr[m] = a[m] * inv;
        }
        __syncthreads();
    }

    float r0 = sr[0], r1 = sr[1], r2 = sr[2], r3 = sr[3], r4 = sr[4];
    float M1 = sM1;
    float sum_v = 0.f, sum_e = 0.f;

    for (int n = tid; n <= t; n += 128) {
        float e = __expf(as[b*kT + n] - M1);
        const float4* hr = (const float4*)(h + ((size_t)b*kS + n)*kD);
        float in0 = 0.f, in1 = 0.f, in2 = 0.f, in3 = 0.f, in4 = 0.f;
        #pragma unroll 8
        for (int d4 = 0; d4 < 32; d4++) {
            float4 hv = __ldg(&hr[d4]);
            int dd = d4 * 4;
            in0 += hv.x*sqs[0][dd] + hv.y*sqs[0][dd+1] + hv.z*sqs[0][dd+2] + hv.w*sqs[0][dd+3];
            in1 += hv.x*sqs[1][dd] + hv.y*sqs[1][dd+1] + hv.z*sqs[1][dd+2] + hv.w*sqs[1][dd+3];
            in2 += hv.x*sqs[2][dd] + hv.y*sqs[2][dd+1] + hv.z*sqs[2][dd+2] + hv.w*sqs[2][dd+3];
            in3 += hv.x*sqs[3][dd] + hv.y*sqs[3][dd+1] + hv.z*sqs[3][dd+2] + hv.w*sqs[3][dd+3];
            in4 += hv.x*sqs[4][dd] + hv.y*sqs[4][dd+1] + hv.z*sqs[4][dd+2] + hv.w*sqs[4][dd+3];
        }
        float s0 = fast_sigmoid(in0);
        float s1 = fast_sigmoid(in1);
        float s2 = fast_sigmoid(in2);
        float s3 = fast_sigmoid(in3);
        float s4 = fast_sigmoid(in4);
        sum_v += e * (r0*s0 + r1*s1 + r2*s2 + r3*s3 + r4*s4);
        sum_e += e;
    }
    #pragma unroll
    for (int o = 16; o; o >>= 1) {
        sum_v += __shfl_down_sync(0xffffffffu, sum_v, o);
        sum_e += __shfl_down_sync(0xffffffffu, sum_e, o);
    }
    if ((tid & 31) == 0) { sv[tid >> 5] = sum_v; se2[tid >> 5] = sum_e; }
    __syncthreads();
    if (tid == 0) {
        float V = sv[0] + sv[1] + sv[2] + sv[3];
        float E = se2[0] + se2[1] + se2[2] + se2[3];
        out[b*kS + t + 1] = V / E;
        if (t == 0) out[b*kS] = 0.f;
    }
}

// ---------------- launch ----------------
extern "C" void kernel_launch(void* const* d_in, const int* in_sizes, int n_in,
                              void* d_out, int out_size)
{
    const int*   question = (const int*)  d_in[0];
    const int*   response = (const int*)  d_in[1];
    const int*   q_nbr    = (const int*)  d_in[3];
    const int*   s_nbr    = (const int*)  d_in[4];
    const int*   qs_sk    = (const int*)  d_in[5];
    const float* emb_q    = (const float*)d_in[6];
    const float* emb_s    = (const float*)d_in[7];
    const float* emb_r    = (const float*)d_in[8];
    const float* W_ih     = (const float*)d_in[9];
    const float* b_ih     = (const float*)d_in[10];
    const float* b_hh     = (const float*)d_in[11];
    const float* ft_W     = (const float*)d_in[12];
    const float* ft_b     = (const float*)d_in[13];
    const float* agg_W    = (const float*)d_in[14];
    const float* agg_b    = (const float*)d_in[15];
    const float* last_W   = (const float*)d_in[16];
    const float* last_b   = (const float*)d_in[17];
    const float* q_W      = (const float*)d_in[18];
    const float* q_b      = (const float*)d_in[19];
    const float* k_W      = (const float*)d_in[20];
    const float* k_b      = (const float*)d_in[21];
    const float* w_W      = (const float*)d_in[22];
    float* out = (float*)d_out;

    float* buf = nullptr;
    cudaGetSymbolAddress((void**)&buf, g_buf);
    float* TA0 = buf + O_TA0;
    float* TA1 = buf + O_TA1;
    float* TA2 = buf + O_TA2;
    float* TB0 = buf + O_TB0;
    float* TB1 = buf + O_TB1;
    float* TC0 = buf + O_TC0;
    float* A   = buf + O_A;

    const int HOP_SMEM = (128*128 + 64*132) * (int)sizeof(float);
    const int RC_SMEM  = (128*128 + 2*32*132 + 128) * (int)sizeof(float);
    static bool attr_done = false;
    if (!attr_done) {
        cudaFuncSetAttribute(hop_kernel, cudaFuncAttributeMaxDynamicSharedMemorySize, HOP_SMEM);
        cudaFuncSetAttribute(rowchain_kernel, cudaFuncAttributeMaxDynamicSharedMemorySize, RC_SMEM);
        attr_done = true;
    }

    prep_kernel<<<1, 512>>>(q_W, q_b, k_W, k_b, w_W, emb_r, W_ih, b_ih, b_hh);

    const int gq = (kNQ + 63) / 64;        // 157
    const int gs = (kNS + 63) / 64;        // 8
    const float iq = 1.f/kQN, is = 1.f/kSN;

    // level 0: TA0, TA2, TA1
    {
        HopParams p;
        p.nt = 3;
        p.t[0] = { emb_q, q_nbr, emb_s, agg_W,           agg_b,       TA0, kQN, iq, kNQ, 0 };
        p.t[1] = { emb_q, q_nbr, emb_s, agg_W + 2*16384, agg_b + 256, TA2, kQN, iq, kNQ, gq };
        p.t[2] = { emb_s, s_nbr, emb_q, agg_W + 16384,   agg_b + 128, TA1, kSN, is, kNS, 2*gq };
        hop_kernel<<<2*gq + gs, 256, HOP_SMEM>>>(p);
    }
    // level 1: TB0, TB1
    {
        HopParams p;
        p.nt = 2;
        p.t[0] = { TA0, q_nbr, TA1, agg_W,         agg_b,       TB0, kQN, iq, kNQ, 0 };
        p.t[1] = { TA1, s_nbr, TA2, agg_W + 16384, agg_b + 128, TB1, kSN, is, kNS, gq };
        p.t[2] = p.t[1];
        hop_kernel<<<gq + gs, 256, HOP_SMEM>>>(p);
    }
    // level 2: TC0
    {
        HopParams p;
        p.nt = 1;
        p.t[0] = { TB0, q_nbr, TB1, agg_W, agg_b, TC0, kQN, iq, kNQ, 0 };
        p.t[1] = p.t[0]; p.t[2] = p.t[0];
        hop_kernel<<<gq, 256, HOP_SMEM>>>(p);
    }
    // last: A
    {
        HopParams p;
        p.nt = 1;
        p.t[0] = { TC0, nullptr, nullptr, last_W, last_b, A, 0, 0.f, kNQ, 0 };
        p.t[1] = p.t[0]; p.t[2] = p.t[0];
        hop_kernel<<<gq, 256, HOP_SMEM>>>(p);
    }

    rowchain_kernel<<<(kB*kS)/32, 256, RC_SMEM>>>(question, response, ft_W, ft_b, W_ih);

    dim3 pg(kT, kB);
    pred_kernel<<<pg, 128>>>(question, qs_sk, emb_q, emb_s, out);
}